// round 3
// baseline (speedup 1.0000x reference)
#include <cuda_runtime.h>
#include <cuda_bf16.h>
#include <cstddef>

#define EPSV 1e-5f
#define NTOK 4096

// Scratch (no allocations allowed): qkv activations and attention+pe output
__device__ float g_qkv[2u * 512u * 4096u];   // 16 MB
__device__ float g_y[2u * 256u * 4096u];     //  8 MB

// ---------------------------------------------------------------------------
// Generic SGEMM + folded BatchNorm epilogue.
// C[b][m][n] = BN( sum_k A[m][k] * B[b][k][n] )
// Block tile 64x64, K-tile 16, 256 threads, 4x4 register tile per thread.
// ---------------------------------------------------------------------------
__global__ __launch_bounds__(256) void gemm_bn_kernel(
    const float* __restrict__ A, const float* __restrict__ B, float* __restrict__ C,
    int M, int N, int K,
    const float* __restrict__ gg, const float* __restrict__ bb,
    const float* __restrict__ mm, const float* __restrict__ vv)
{
    __shared__ float sA[16][68];   // A^T tile: [kk][m], padded (272B rows, 16B-aligned)
    __shared__ float sB[16][64];   // B tile:  [kk][n]

    const int tid = threadIdx.x;
    const int tn = tid & 15;       // n-tile index (x4)
    const int tm = tid >> 4;       // m-tile index (x4)
    const int m0 = blockIdx.y * 64, n0 = blockIdx.x * 64;
    const float* Bp = B + (size_t)blockIdx.z * (size_t)K * N;
    float* Cp = C + (size_t)blockIdx.z * (size_t)M * N;

    const int lm = tid >> 2;           // 0..63  (A-load row)
    const int lk = (tid & 3) << 2;     // 0,4,8,12 (A-load col, float4)

    float acc[4][4] = {};

    for (int k0 = 0; k0 < K; k0 += 16) {
        // Load A tile (64 x 16), transpose into sA[kk][m]
        float4 a4 = *(const float4*)&A[(size_t)(m0 + lm) * K + k0 + lk];
        sA[lk + 0][lm] = a4.x; sA[lk + 1][lm] = a4.y;
        sA[lk + 2][lm] = a4.z; sA[lk + 3][lm] = a4.w;
        // Load B tile (16 x 64), natural layout (coalesced)
        #pragma unroll
        for (int r = 0; r < 4; r++) {
            int kk = r * 4 + (tid >> 6);
            int nn = tid & 63;
            sB[kk][nn] = Bp[(size_t)(k0 + kk) * N + n0 + nn];
        }
        __syncthreads();

        #pragma unroll
        for (int kk = 0; kk < 16; kk++) {
            float4 av = *(const float4*)&sA[kk][tm << 2];
            float4 bv = *(const float4*)&sB[kk][tn << 2];
            float a_[4] = {av.x, av.y, av.z, av.w};
            float b_[4] = {bv.x, bv.y, bv.z, bv.w};
            #pragma unroll
            for (int i = 0; i < 4; i++)
                #pragma unroll
                for (int j = 0; j < 4; j++)
                    acc[i][j] += a_[i] * b_[j];
        }
        __syncthreads();
    }

    #pragma unroll
    for (int i = 0; i < 4; i++) {
        int m = m0 + (tm << 2) + i;
        float sc = gg[m] * rsqrtf(vv[m] + EPSV);
        float sh = bb[m] - mm[m] * sc;
        float4 o;
        o.x = acc[i][0] * sc + sh;
        o.y = acc[i][1] * sc + sh;
        o.z = acc[i][2] * sc + sh;
        o.w = acc[i][3] * sc + sh;
        *(float4*)&Cp[(size_t)m * N + n0 + (tn << 2)] = o;
    }
}

// ---------------------------------------------------------------------------
// Flash attention. One CTA = one (b,h) x 64-query block. 256 threads.
// qkv layout per (b): 512 rows x 4096 cols; head h occupies rows [h*128, h*128+128):
//   q = rows +0..32, k = rows +32..64, v = rows +64..128.
// Output: g_y[(bh*64 + d) * 4096 + token]
// ---------------------------------------------------------------------------
__global__ __launch_bounds__(256) void attn_kernel(
    const float* __restrict__ qkv, float* __restrict__ y)
{
    extern __shared__ float sm[];
    float* sQ  = sm;               // 32 x 64   (scaled Q, [d][q])
    float* sK  = sQ  + 32 * 64;    // 32 x 64   ([d][k])
    float* sVt = sK  + 32 * 64;    // 64 x 64   ([k][d], XOR-swizzled cols)
    float* sP  = sVt + 64 * 64;    // 64 x 64   ([k][q], XOR-swizzled cols)
    float* sM  = sP  + 64 * 64;    // 64 running max
    float* sL  = sM  + 64;         // 64 running denom
    float* sAl = sL  + 64;         // 64 rescale factor

    const int tid = threadIdx.x;
    const int bh = blockIdx.y;                    // b*4 + h
    const int bi = bh >> 2, h = bh & 3;
    const float* qp = qkv + ((size_t)bi * 512 + h * 128) * NTOK;
    const float* kp = qp + (size_t)32 * NTOK;
    const float* vp = qp + (size_t)64 * NTOK;
    const int q0 = blockIdx.x * 64;
    const float scale = 0.17677669529663687f;     // 1/sqrt(32)

    // Load Q tile (pre-scaled)
    for (int e = tid; e < 32 * 64; e += 256) {
        int d = e >> 6, j = e & 63;
        sQ[d * 64 + j] = qp[(size_t)d * NTOK + q0 + j] * scale;
    }
    if (tid < 64) { sM[tid] = -1e30f; sL[tid] = 0.f; }

    const int tk = tid & 15;   // key  group (phase S) / dim group (phase AV)
    const int tq = tid >> 4;   // query group (both phases)

    float acc[4][4] = {};      // [dim][query]
    __syncthreads();

    for (int kb = 0; kb < NTOK / 64; kb++) {
        const int j0 = kb * 64;
        // Load K (natural) and V (transposed+swizzled: sVt[key][dim])
        for (int e = tid; e < 32 * 64; e += 256) {
            int d = e >> 6, j = e & 63;
            sK[d * 64 + j] = kp[(size_t)d * NTOK + j0 + j];
        }
        for (int e = tid; e < 64 * 64; e += 256) {
            int d = e >> 6, j = e & 63;
            sVt[j * 64 + (d ^ ((j & 7) << 2))] = vp[(size_t)d * NTOK + j0 + j];
        }
        __syncthreads();

        // ---- S = (Q*scale)^T K : s[ii][jj], query 4tq+ii, key 4tk+jj ----
        float s[4][4] = {};
        #pragma unroll
        for (int d = 0; d < 32; d++) {
            float4 av = *(const float4*)&sQ[d * 64 + (tq << 2)];
            float4 bv = *(const float4*)&sK[d * 64 + (tk << 2)];
            float a_[4] = {av.x, av.y, av.z, av.w};
            float b_[4] = {bv.x, bv.y, bv.z, bv.w};
            #pragma unroll
            for (int i = 0; i < 4; i++)
                #pragma unroll
                for (int j = 0; j < 4; j++)
                    s[i][j] += a_[i] * b_[j];
        }

        // ---- online softmax: reduce across the 16 lanes sharing tq ----
        #pragma unroll
        for (int ii = 0; ii < 4; ii++) {
            float mx = fmaxf(fmaxf(s[ii][0], s[ii][1]), fmaxf(s[ii][2], s[ii][3]));
            #pragma unroll
            for (int o = 1; o < 16; o <<= 1)
                mx = fmaxf(mx, __shfl_xor_sync(0xffffffffu, mx, o));
            const int qi = (tq << 2) + ii;
            float mo = sM[qi];
            float mn = fmaxf(mo, mx);
            float sum = 0.f;
            #pragma unroll
            for (int jj = 0; jj < 4; jj++) {
                float p = __expf(s[ii][jj] - mn);
                s[ii][jj] = p;
                sum += p;
            }
            #pragma unroll
            for (int o = 1; o < 16; o <<= 1)
                sum += __shfl_xor_sync(0xffffffffu, sum, o);
            float al = __expf(mo - mn);
            if (tk == 0) {
                sM[qi] = mn;
                sAl[qi] = al;
                sL[qi] = sL[qi] * al + sum;
            }
        }
        // write P: sP[key][query], swizzled
        #pragma unroll
        for (int jj = 0; jj < 4; jj++) {
            int r = (tk << 2) + jj;
            int c = (tq << 2) ^ ((r & 7) << 2);
            float4 pv = make_float4(s[0][jj], s[1][jj], s[2][jj], s[3][jj]);
            *(float4*)&sP[r * 64 + c] = pv;
        }
        __syncthreads();

        // ---- rescale + AV:  acc[dim][q] = acc*alpha + V[dim][k] P[k][q] ----
        float al[4];
        #pragma unroll
        for (int j = 0; j < 4; j++) al[j] = sAl[(tq << 2) + j];
        #pragma unroll
        for (int i = 0; i < 4; i++)
            #pragma unroll
            for (int j = 0; j < 4; j++)
                acc[i][j] *= al[j];

        #pragma unroll
        for (int k = 0; k < 64; k++) {
            int sw = (k & 7) << 2;
            float4 av = *(const float4*)&sVt[k * 64 + ((tk << 2) ^ sw)];
            float4 bv = *(const float4*)&sP[k * 64 + ((tq << 2) ^ sw)];
            float a_[4] = {av.x, av.y, av.z, av.w};
            float b_[4] = {bv.x, bv.y, bv.z, bv.w};
            #pragma unroll
            for (int i = 0; i < 4; i++)
                #pragma unroll
                for (int j = 0; j < 4; j++)
                    acc[i][j] += a_[i] * b_[j];
        }
        __syncthreads();
    }

    // epilogue: divide by denom, write y
    float linv[4];
    #pragma unroll
    for (int j = 0; j < 4; j++) linv[j] = 1.f / sL[(tq << 2) + j];
    #pragma unroll
    for (int i = 0; i < 4; i++) {
        int d = (tk << 2) + i;
        float4 o = make_float4(acc[i][0] * linv[0], acc[i][1] * linv[1],
                               acc[i][2] * linv[2], acc[i][3] * linv[3]);
        *(float4*)&y[((size_t)(bh * 64 + d)) * NTOK + q0 + (tq << 2)] = o;
    }
}

// ---------------------------------------------------------------------------
// Depthwise 3x3 conv (pad 1) on V channels + BN, accumulated into g_y.
// V channel c (0..255): head = c/64, dim = c%64 -> qkv row head*128 + 64 + dim
// Layout per batch: 256 channels * 4096 pixels = 1<<20 elements.
// ---------------------------------------------------------------------------
__global__ __launch_bounds__(256) void pe_kernel(
    const float* __restrict__ qkv, float* __restrict__ y,
    const float* __restrict__ w,
    const float* __restrict__ gg, const float* __restrict__ bb,
    const float* __restrict__ mm, const float* __restrict__ vv)
{
    const int idx = blockIdx.x * 256 + threadIdx.x;   // (bi, c, pix)
    const int bi = idx >> 20;                         // / (256*4096)
    const int r  = idx & ((1 << 20) - 1);
    const int c  = r >> 12;
    const int pix = r & 4095;
    const int py = pix >> 6, px = pix & 63;
    const int head = c >> 6, dim = c & 63;

    const float* vch = qkv + ((size_t)bi * 512 + head * 128 + 64 + dim) * NTOK;
    const float* wc = w + c * 9;

    float s = 0.f;
    #pragma unroll
    for (int dy = -1; dy <= 1; dy++) {
        int yy = py + dy;
        if (yy < 0 || yy > 63) continue;
        #pragma unroll
        for (int dx = -1; dx <= 1; dx++) {
            int xx = px + dx;
            if (xx < 0 || xx > 63) continue;
            s += vch[yy * 64 + xx] * wc[(dy + 1) * 3 + (dx + 1)];
        }
    }
    float sc = gg[c] * rsqrtf(vv[c] + EPSV);
    float val = s * sc + (bb[c] - mm[c] * sc);
    y[idx] += val;
}

// ---------------------------------------------------------------------------
extern "C" void kernel_launch(void* const* d_in, const int* in_sizes, int n_in,
                              void* d_out, int out_size)
{
    const float* x      = (const float*)d_in[0];
    const float* qkv_w  = (const float*)d_in[1];
    const float* qkv_g  = (const float*)d_in[2];
    const float* qkv_b  = (const float*)d_in[3];
    const float* qkv_m  = (const float*)d_in[4];
    const float* qkv_v  = (const float*)d_in[5];
    const float* proj_w = (const float*)d_in[6];
    const float* proj_g = (const float*)d_in[7];
    const float* proj_b = (const float*)d_in[8];
    const float* proj_m = (const float*)d_in[9];
    const float* proj_v = (const float*)d_in[10];
    const float* pe_w   = (const float*)d_in[11];
    const float* pe_g   = (const float*)d_in[12];
    const float* pe_b   = (const float*)d_in[13];
    const float* pe_m   = (const float*)d_in[14];
    const float* pe_v   = (const float*)d_in[15];
    float* out = (float*)d_out;

    float* qkv_ptr = nullptr;
    float* y_ptr = nullptr;
    cudaGetSymbolAddress((void**)&qkv_ptr, g_qkv);
    cudaGetSymbolAddress((void**)&y_ptr, g_y);

    const int attn_smem = (32 * 64 * 2 + 64 * 64 * 2 + 3 * 64) * (int)sizeof(float); // 49920
    cudaFuncSetAttribute(attn_kernel, cudaFuncAttributeMaxDynamicSharedMemorySize, attn_smem);

    // 1) QKV 1x1 conv + BN:  (512 x 256) @ (256 x 4096) per batch
    gemm_bn_kernel<<<dim3(64, 8, 2), 256>>>(qkv_w, x, qkv_ptr, 512, 4096, 256,
                                            qkv_g, qkv_b, qkv_m, qkv_v);
    // 2) attention -> g_y
    attn_kernel<<<dim3(64, 8), 256, attn_smem>>>(qkv_ptr, y_ptr);
    // 3) PE depthwise conv + BN, accumulate into g_y
    pe_kernel<<<8192, 256>>>(qkv_ptr, y_ptr, pe_w, pe_g, pe_b, pe_m, pe_v);
    // 4) proj 1x1 conv + BN -> out
    gemm_bn_kernel<<<dim3(64, 4, 2), 256>>>(proj_w, y_ptr, out, 256, 4096, 256,
                                            proj_g, proj_b, proj_m, proj_v);
}

// round 5
// speedup vs baseline: 2.2641x; 2.2641x over previous
#include <cuda_runtime.h>
#include <cuda_bf16.h>
#include <cstdint>
#include <cstddef>

#define EPSV 1e-5f
#define NTOK 4096

// Scratch (no allocations allowed)
__device__ float g_qkv[2u * 512u * 4096u];   // 16 MB fp32 qkv activations
__device__ float g_y[2u * 256u * 4096u];     //  8 MB attention + pe output

// ---------------------------------------------------------------------------
// bf16 hi/lo helpers
// ---------------------------------------------------------------------------
__device__ __forceinline__ uint32_t pack_hi(float a, float b, uint32_t& lo) {
    __nv_bfloat16 ah = __float2bfloat16_rn(a), bh = __float2bfloat16_rn(b);
    __nv_bfloat16 al = __float2bfloat16_rn(a - __bfloat162float(ah));
    __nv_bfloat16 bl = __float2bfloat16_rn(b - __bfloat162float(bh));
    __nv_bfloat162 H = __halves2bfloat162(ah, bh);
    __nv_bfloat162 L = __halves2bfloat162(al, bl);
    lo = *reinterpret_cast<uint32_t*>(&L);
    return *reinterpret_cast<uint32_t*>(&H);
}

// mma.sync m16n8k16 row.col f32 += bf16*bf16
__device__ __forceinline__ void mma16816(float* c, const uint32_t* a, const uint32_t* b) {
    asm volatile(
        "mma.sync.aligned.m16n8k16.row.col.f32.bf16.bf16.f32 "
        "{%0,%1,%2,%3}, {%4,%5,%6,%7}, {%8,%9}, {%0,%1,%2,%3};"
        : "+f"(c[0]), "+f"(c[1]), "+f"(c[2]), "+f"(c[3])
        : "r"(a[0]), "r"(a[1]), "r"(a[2]), "r"(a[3]), "r"(b[0]), "r"(b[1]));
}

// ---------------------------------------------------------------------------
// Flash attention via warp-level bf16 HMMA with hi/lo 3-term split.
// CTA = (b,h) x 128-query tile, 256 threads (8 warps x 16 query rows).
// qkv per batch: 512 rows x 4096 tokens; head h rows [h*128, h*128+128):
//   q rows +0..31, k rows +32..63, v rows +64..127.
// ---------------------------------------------------------------------------
__global__ __launch_bounds__(256, 1) void attn_mma_kernel(
    const float* __restrict__ qkv, float* __restrict__ y)
{
    // u32 = bf16x2. Row strides chosen for conflict-free B-fragment reads.
    __shared__ uint32_t sQ[128][33];   // [row][dimpair]: hi 0..15, lo 16..31
    __shared__ uint32_t sK[64][36];    // [key][dimpair]: hi 0..15, lo 16..31
    __shared__ uint32_t sV[64][68];    // [dim][keypair]: hi 0..31, lo 32..63

    const int tid = threadIdx.x, wid = tid >> 5, lane = tid & 31;
    const int tg = lane >> 2;          // 0..7
    const int t4 = lane & 3;           // 0..3
    const int bh = blockIdx.y, bi = bh >> 2, h = bh & 3;
    const int q0 = blockIdx.x * 128;

    const float* qp = qkv + ((size_t)bi * 512 + h * 128) * NTOK;
    const float* kp = qp + (size_t)32 * NTOK;
    const float* vp = qp + (size_t)64 * NTOK;

    // ---- stage Q (scale folded), hi/lo split ----
    {
        const float scale = 0.17677669529663687f;   // 1/sqrt(32)
        int row = tid & 127, dp0 = tid >> 7;        // dp0 in {0,1}
        #pragma unroll
        for (int dp = dp0; dp < 16; dp += 2) {
            float x0 = qp[(size_t)(2 * dp) * NTOK + q0 + row] * scale;
            float x1 = qp[(size_t)(2 * dp + 1) * NTOK + q0 + row] * scale;
            uint32_t lo, hi = pack_hi(x0, x1, lo);
            sQ[row][dp] = hi;
            sQ[row][16 + dp] = lo;
        }
    }
    __syncthreads();

    // ---- Q fragments (register resident for whole kernel) ----
    uint32_t qh[2][4], ql[2][4];
    {
        int r0 = wid * 16 + tg, r1 = r0 + 8;
        #pragma unroll
        for (int ks = 0; ks < 2; ks++) {
            int c = t4 + 8 * ks;
            qh[ks][0] = sQ[r0][c];          qh[ks][1] = sQ[r1][c];
            qh[ks][2] = sQ[r0][c + 4];      qh[ks][3] = sQ[r1][c + 4];
            ql[ks][0] = sQ[r0][16 + c];     ql[ks][1] = sQ[r1][16 + c];
            ql[ks][2] = sQ[r0][16 + c + 4]; ql[ks][3] = sQ[r1][16 + c + 4];
        }
    }

    // online softmax state (rows r0 = tg, r1 = tg+8 of this warp's slab;
    // replicated across the 4 lanes of each quad)
    float m0 = -3e38f, m1 = -3e38f, l0 = 0.f, l1 = 0.f;
    float yacc[8][4];                  // [dim-tile][frag]
    #pragma unroll
    for (int i = 0; i < 8; i++)
        #pragma unroll
        for (int j = 0; j < 4; j++) yacc[i][j] = 0.f;

    for (int blk = 0; blk < 64; blk++) {
        const int k0t = blk * 64;
        // ---- stage K block: 64 keys x 32 dims, hi/lo ----
        {
            int key = tid & 63, dp0 = tid >> 6;     // dp0 in 0..3
            #pragma unroll
            for (int dp = dp0; dp < 16; dp += 4) {
                float x0 = kp[(size_t)(2 * dp) * NTOK + k0t + key];
                float x1 = kp[(size_t)(2 * dp + 1) * NTOK + k0t + key];
                uint32_t lo, hi = pack_hi(x0, x1, lo);
                sK[key][dp] = hi;
                sK[key][16 + dp] = lo;
            }
        }
        // ---- stage V block: 64 dims x 64 keys, hi/lo, [dim][keypair] ----
        {
            int kpair = tid & 31, d0 = tid >> 5;    // d0 in 0..7
            #pragma unroll
            for (int d = d0; d < 64; d += 8) {
                float2 x = *(const float2*)(vp + (size_t)d * NTOK + k0t + 2 * kpair);
                uint32_t lo, hi = pack_hi(x.x, x.y, lo);
                sV[d][kpair] = hi;
                sV[d][32 + kpair] = lo;
            }
        }
        __syncthreads();

        // ---- S = Q K^T (3-term hi/lo), per warp: 16 x 64 ----
        float s[8][4];
        #pragma unroll
        for (int nt = 0; nt < 8; nt++) {
            s[nt][0] = s[nt][1] = s[nt][2] = s[nt][3] = 0.f;
            int key = nt * 8 + tg;
            #pragma unroll
            for (int ks = 0; ks < 2; ks++) {
                uint32_t bh_[2] = { sK[key][t4 + 8 * ks], sK[key][t4 + 4 + 8 * ks] };
                uint32_t bl_[2] = { sK[key][16 + t4 + 8 * ks], sK[key][16 + t4 + 4 + 8 * ks] };
                mma16816(s[nt], qh[ks], bh_);
                mma16816(s[nt], qh[ks], bl_);
                mma16816(s[nt], ql[ks], bh_);
            }
        }

        // ---- online softmax update ----
        float mx0 = -3e38f, mx1 = -3e38f;
        #pragma unroll
        for (int nt = 0; nt < 8; nt++) {
            mx0 = fmaxf(mx0, fmaxf(s[nt][0], s[nt][1]));
            mx1 = fmaxf(mx1, fmaxf(s[nt][2], s[nt][3]));
        }
        mx0 = fmaxf(mx0, __shfl_xor_sync(0xffffffffu, mx0, 1));
        mx0 = fmaxf(mx0, __shfl_xor_sync(0xffffffffu, mx0, 2));
        mx1 = fmaxf(mx1, __shfl_xor_sync(0xffffffffu, mx1, 1));
        mx1 = fmaxf(mx1, __shfl_xor_sync(0xffffffffu, mx1, 2));
        float mn0 = fmaxf(m0, mx0), mn1 = fmaxf(m1, mx1);
        float al0 = __expf(m0 - mn0), al1 = __expf(m1 - mn1);
        m0 = mn0; m1 = mn1;

        uint32_t ph01[8], pl01[8], ph23[8], pl23[8];
        float sum0 = 0.f, sum1 = 0.f;
        #pragma unroll
        for (int nt = 0; nt < 8; nt++) {
            float p0 = __expf(s[nt][0] - mn0);
            float p1 = __expf(s[nt][1] - mn0);
            float p2 = __expf(s[nt][2] - mn1);
            float p3 = __expf(s[nt][3] - mn1);
            sum0 += p0 + p1;  sum1 += p2 + p3;
            ph01[nt] = pack_hi(p0, p1, pl01[nt]);
            ph23[nt] = pack_hi(p2, p3, pl23[nt]);
        }
        sum0 += __shfl_xor_sync(0xffffffffu, sum0, 1);
        sum0 += __shfl_xor_sync(0xffffffffu, sum0, 2);
        sum1 += __shfl_xor_sync(0xffffffffu, sum1, 1);
        sum1 += __shfl_xor_sync(0xffffffffu, sum1, 2);
        l0 = l0 * al0 + sum0;
        l1 = l1 * al1 + sum1;

        // rescale Y
        #pragma unroll
        for (int dt = 0; dt < 8; dt++) {
            yacc[dt][0] *= al0; yacc[dt][1] *= al0;
            yacc[dt][2] *= al1; yacc[dt][3] *= al1;
        }

        // ---- Y += P V^T (3-term hi/lo): k = 64 keys in 4 k-steps ----
        #pragma unroll
        for (int ks = 0; ks < 4; ks++) {
            uint32_t ah[4]  = { ph01[2 * ks], ph23[2 * ks], ph01[2 * ks + 1], ph23[2 * ks + 1] };
            uint32_t alo[4] = { pl01[2 * ks], pl23[2 * ks], pl01[2 * ks + 1], pl23[2 * ks + 1] };
            #pragma unroll
            for (int dt = 0; dt < 8; dt++) {
                int dim = dt * 8 + tg;
                uint32_t bh_[2] = { sV[dim][t4 + 8 * ks], sV[dim][t4 + 4 + 8 * ks] };
                uint32_t bl_[2] = { sV[dim][32 + t4 + 8 * ks], sV[dim][32 + t4 + 4 + 8 * ks] };
                mma16816(yacc[dt], ah, bh_);
                mma16816(yacc[dt], ah, bl_);
                mma16816(yacc[dt], alo, bh_);
            }
        }
        __syncthreads();   // protect sK/sV before next staging
    }

    // ---- epilogue: divide by denom, write y ----
    float li0 = 1.f / l0, li1 = 1.f / l1;
    int tok0 = q0 + wid * 16 + tg;
    #pragma unroll
    for (int dt = 0; dt < 8; dt++) {
        int dim = dt * 8 + t4 * 2;
        float* o = y + ((size_t)(bh * 64 + dim)) * NTOK;
        o[tok0]            = yacc[dt][0] * li0;
        o[NTOK + tok0]     = yacc[dt][1] * li0;
        o[tok0 + 8]        = yacc[dt][2] * li1;
        o[NTOK + tok0 + 8] = yacc[dt][3] * li1;
    }
}

// ---------------------------------------------------------------------------
// SGEMM + folded BatchNorm (unchanged from passing R3 kernel)
// ---------------------------------------------------------------------------
__global__ __launch_bounds__(256) void gemm_bn_kernel(
    const float* __restrict__ A, const float* __restrict__ B, float* __restrict__ C,
    int M, int N, int K,
    const float* __restrict__ gg, const float* __restrict__ bb,
    const float* __restrict__ mm, const float* __restrict__ vv)
{
    __shared__ float sA[16][68];
    __shared__ float sB[16][64];

    const int tid = threadIdx.x;
    const int tn = tid & 15;
    const int tm = tid >> 4;
    const int m0 = blockIdx.y * 64, n0 = blockIdx.x * 64;
    const float* Bp = B + (size_t)blockIdx.z * (size_t)K * N;
    float* Cp = C + (size_t)blockIdx.z * (size_t)M * N;

    const int lm = tid >> 2;
    const int lk = (tid & 3) << 2;

    float acc[4][4] = {};

    for (int k0 = 0; k0 < K; k0 += 16) {
        float4 a4 = *(const float4*)&A[(size_t)(m0 + lm) * K + k0 + lk];
        sA[lk + 0][lm] = a4.x; sA[lk + 1][lm] = a4.y;
        sA[lk + 2][lm] = a4.z; sA[lk + 3][lm] = a4.w;
        #pragma unroll
        for (int r = 0; r < 4; r++) {
            int kk = r * 4 + (tid >> 6);
            int nn = tid & 63;
            sB[kk][nn] = Bp[(size_t)(k0 + kk) * N + n0 + nn];
        }
        __syncthreads();
        #pragma unroll
        for (int kk = 0; kk < 16; kk++) {
            float4 av = *(const float4*)&sA[kk][tm << 2];
            float4 bv = *(const float4*)&sB[kk][tn << 2];
            float a_[4] = {av.x, av.y, av.z, av.w};
            float b_[4] = {bv.x, bv.y, bv.z, bv.w};
            #pragma unroll
            for (int i = 0; i < 4; i++)
                #pragma unroll
                for (int j = 0; j < 4; j++)
                    acc[i][j] += a_[i] * b_[j];
        }
        __syncthreads();
    }
    #pragma unroll
    for (int i = 0; i < 4; i++) {
        int m = m0 + (tm << 2) + i;
        float sc = gg[m] * rsqrtf(vv[m] + EPSV);
        float sh = bb[m] - mm[m] * sc;
        float4 o;
        o.x = acc[i][0] * sc + sh;
        o.y = acc[i][1] * sc + sh;
        o.z = acc[i][2] * sc + sh;
        o.w = acc[i][3] * sc + sh;
        *(float4*)&Cp[(size_t)m * N + n0 + (tn << 2)] = o;
    }
}

// ---------------------------------------------------------------------------
// Depthwise 3x3 conv + BN accumulated into g_y (unchanged)
// ---------------------------------------------------------------------------
__global__ __launch_bounds__(256) void pe_kernel(
    const float* __restrict__ qkv, float* __restrict__ y,
    const float* __restrict__ w,
    const float* __restrict__ gg, const float* __restrict__ bb,
    const float* __restrict__ mm, const float* __restrict__ vv)
{
    const int idx = blockIdx.x * 256 + threadIdx.x;
    const int bi = idx >> 20;
    const int r  = idx & ((1 << 20) - 1);
    const int c  = r >> 12;
    const int pix = r & 4095;
    const int py = pix >> 6, px = pix & 63;
    const int head = c >> 6, dim = c & 63;

    const float* vch = qkv + ((size_t)bi * 512 + head * 128 + 64 + dim) * NTOK;
    const float* wc = w + c * 9;

    float s = 0.f;
    #pragma unroll
    for (int dy = -1; dy <= 1; dy++) {
        int yy = py + dy;
        if (yy < 0 || yy > 63) continue;
        #pragma unroll
        for (int dx = -1; dx <= 1; dx++) {
            int xx = px + dx;
            if (xx < 0 || xx > 63) continue;
            s += vch[yy * 64 + xx] * wc[(dy + 1) * 3 + (dx + 1)];
        }
    }
    float sc = gg[c] * rsqrtf(vv[c] + EPSV);
    y[idx] += s * sc + (bb[c] - mm[c] * sc);
}

// ---------------------------------------------------------------------------
extern "C" void kernel_launch(void* const* d_in, const int* in_sizes, int n_in,
                              void* d_out, int out_size)
{
    const float* x      = (const float*)d_in[0];
    const float* qkv_w  = (const float*)d_in[1];
    const float* qkv_g  = (const float*)d_in[2];
    const float* qkv_b  = (const float*)d_in[3];
    const float* qkv_m  = (const float*)d_in[4];
    const float* qkv_v  = (const float*)d_in[5];
    const float* proj_w = (const float*)d_in[6];
    const float* proj_g = (const float*)d_in[7];
    const float* proj_b = (const float*)d_in[8];
    const float* proj_m = (const float*)d_in[9];
    const float* proj_v = (const float*)d_in[10];
    const float* pe_w   = (const float*)d_in[11];
    const float* pe_g   = (const float*)d_in[12];
    const float* pe_b   = (const float*)d_in[13];
    const float* pe_m   = (const float*)d_in[14];
    const float* pe_v   = (const float*)d_in[15];
    float* out = (float*)d_out;

    float* qkv_ptr = nullptr;
    float* y_ptr = nullptr;
    cudaGetSymbolAddress((void**)&qkv_ptr, g_qkv);
    cudaGetSymbolAddress((void**)&y_ptr, g_y);

    // 1) QKV 1x1 conv + BN
    gemm_bn_kernel<<<dim3(64, 8, 2), 256>>>(qkv_w, x, qkv_ptr, 512, 4096, 256,
                                            qkv_g, qkv_b, qkv_m, qkv_v);
    // 2) HMMA flash attention -> g_y
    attn_mma_kernel<<<dim3(32, 8), 256>>>(qkv_ptr, y_ptr);
    // 3) PE depthwise conv + BN accumulate
    pe_kernel<<<8192, 256>>>(qkv_ptr, y_ptr, pe_w, pe_g, pe_b, pe_m, pe_v);
    // 4) proj 1x1 conv + BN -> out
    gemm_bn_kernel<<<dim3(64, 4, 2), 256>>>(proj_w, y_ptr, out, 256, 4096, 256,
                                            proj_g, proj_b, proj_m, proj_v);
}

// round 6
// speedup vs baseline: 2.4890x; 1.0993x over previous
#include <cuda_runtime.h>
#include <cuda_bf16.h>
#include <cuda_fp16.h>
#include <cstdint>
#include <cstddef>

#define EPSV 1e-5f
#define NTOK 4096

// Scratch (no allocations allowed)
__device__ float g_qkv[2u * 512u * 4096u];   // 16 MB fp32 qkv activations
__device__ float g_y[2u * 256u * 4096u];     //  8 MB attention + pe output

__device__ __forceinline__ uint32_t pack_h2(float a, float b) {
    __half2 h = __floats2half2_rn(a, b);
    return *reinterpret_cast<uint32_t*>(&h);
}

// mma.sync m16n8k16 row.col f32 += f16*f16
__device__ __forceinline__ void mma16816(float* c, const uint32_t* a, const uint32_t* b) {
    asm volatile(
        "mma.sync.aligned.m16n8k16.row.col.f32.f16.f16.f32 "
        "{%0,%1,%2,%3}, {%4,%5,%6,%7}, {%8,%9}, {%0,%1,%2,%3};"
        : "+f"(c[0]), "+f"(c[1]), "+f"(c[2]), "+f"(c[3])
        : "r"(a[0]), "r"(a[1]), "r"(a[2]), "r"(a[3]), "r"(b[0]), "r"(b[1]));
}

// ---------------------------------------------------------------------------
// Flash attention via warp-level fp16 HMMA (single-term).
// CTA = (b,h) x 128-query tile, 256 threads (8 warps x 16 query rows).
// qkv per batch: 512 rows x 4096 tokens; head h rows [h*128, h*128+128):
//   q rows +0..31, k rows +32..63, v rows +64..127.
// ---------------------------------------------------------------------------
__global__ __launch_bounds__(256, 1) void attn_mma_kernel(
    const float* __restrict__ qkv, float* __restrict__ y)
{
    // u32 = half2. Row pads chosen so B-fragment LDS are conflict-free:
    // sK stride 20: bank(20*tg + t4) = {4a}+{0..3} distinct; sV stride 36: {4k+t4} distinct.
    __shared__ uint32_t sQ[128][20];   // [row][dimpair 0..15]
    __shared__ uint32_t sK[64][20];    // [key][dimpair 0..15]
    __shared__ uint32_t sV[64][36];    // [dim][keypair 0..31]

    const int tid = threadIdx.x, wid = tid >> 5, lane = tid & 31;
    const int tg = lane >> 2;          // 0..7
    const int t4 = lane & 3;           // 0..3
    const int bh = blockIdx.y, bi = bh >> 2, h = bh & 3;
    const int q0 = blockIdx.x * 128;

    const float* qp = qkv + ((size_t)bi * 512 + h * 128) * NTOK;
    const float* kp = qp + (size_t)32 * NTOK;
    const float* vp = qp + (size_t)64 * NTOK;

    // ---- stage Q (scale folded) ----
    {
        const float scale = 0.17677669529663687f;   // 1/sqrt(32)
        int row = tid & 127, dp0 = tid >> 7;        // dp0 in {0,1}
        #pragma unroll
        for (int dp = dp0; dp < 16; dp += 2) {
            float x0 = qp[(size_t)(2 * dp) * NTOK + q0 + row] * scale;
            float x1 = qp[(size_t)(2 * dp + 1) * NTOK + q0 + row] * scale;
            sQ[row][dp] = pack_h2(x0, x1);
        }
    }
    __syncthreads();

    // ---- Q fragments (register resident) ----
    uint32_t qh[2][4];
    {
        int r0 = wid * 16 + tg, r1 = r0 + 8;
        #pragma unroll
        for (int ks = 0; ks < 2; ks++) {
            int c = t4 + 8 * ks;
            qh[ks][0] = sQ[r0][c];     qh[ks][1] = sQ[r1][c];
            qh[ks][2] = sQ[r0][c + 4]; qh[ks][3] = sQ[r1][c + 4];
        }
    }

    // staging index precompute
    const int kkey = tid & 63, kdp0 = tid >> 6;     // K: 4 dp rows per thread
    const int vkp = tid & 31, vd0 = tid >> 5;       // V: 8 dims per thread

    float kx[4][2];
    float2 vx[8];
    // preload block 0
    {
        #pragma unroll
        for (int i = 0; i < 4; i++) {
            int dp = kdp0 + 4 * i;
            kx[i][0] = kp[(size_t)(2 * dp) * NTOK + kkey];
            kx[i][1] = kp[(size_t)(2 * dp + 1) * NTOK + kkey];
        }
        #pragma unroll
        for (int i = 0; i < 8; i++) {
            int d = vd0 + 8 * i;
            vx[i] = *(const float2*)(vp + (size_t)d * NTOK + 2 * vkp);
        }
    }

    // online softmax state
    float m0 = -3e38f, m1 = -3e38f, l0 = 0.f, l1 = 0.f;
    float yacc[8][4];
    #pragma unroll
    for (int i = 0; i < 8; i++)
        #pragma unroll
        for (int j = 0; j < 4; j++) yacc[i][j] = 0.f;

    for (int blk = 0; blk < 64; blk++) {
        // ---- store staged regs -> smem (convert to fp16) ----
        __syncthreads();   // previous compute done reading smem
        #pragma unroll
        for (int i = 0; i < 4; i++)
            sK[kkey][kdp0 + 4 * i] = pack_h2(kx[i][0], kx[i][1]);
        #pragma unroll
        for (int i = 0; i < 8; i++)
            sV[vd0 + 8 * i][vkp] = pack_h2(vx[i].x, vx[i].y);
        __syncthreads();

        // ---- preload next block (overlaps with mma below) ----
        if (blk < 63) {
            const int k0t = (blk + 1) * 64;
            #pragma unroll
            for (int i = 0; i < 4; i++) {
                int dp = kdp0 + 4 * i;
                kx[i][0] = kp[(size_t)(2 * dp) * NTOK + k0t + kkey];
                kx[i][1] = kp[(size_t)(2 * dp + 1) * NTOK + k0t + kkey];
            }
            #pragma unroll
            for (int i = 0; i < 8; i++) {
                int d = vd0 + 8 * i;
                vx[i] = *(const float2*)(vp + (size_t)d * NTOK + k0t + 2 * vkp);
            }
        }

        // ---- S = Q K^T, per warp: 16 x 64 ----
        float s[8][4];
        #pragma unroll
        for (int nt = 0; nt < 8; nt++) {
            s[nt][0] = s[nt][1] = s[nt][2] = s[nt][3] = 0.f;
            int key = nt * 8 + tg;
            #pragma unroll
            for (int ks = 0; ks < 2; ks++) {
                uint32_t b_[2] = { sK[key][t4 + 8 * ks], sK[key][t4 + 4 + 8 * ks] };
                mma16816(s[nt], qh[ks], b_);
            }
        }

        // ---- online softmax update ----
        float mx0 = -3e38f, mx1 = -3e38f;
        #pragma unroll
        for (int nt = 0; nt < 8; nt++) {
            mx0 = fmaxf(mx0, fmaxf(s[nt][0], s[nt][1]));
            mx1 = fmaxf(mx1, fmaxf(s[nt][2], s[nt][3]));
        }
        mx0 = fmaxf(mx0, __shfl_xor_sync(0xffffffffu, mx0, 1));
        mx0 = fmaxf(mx0, __shfl_xor_sync(0xffffffffu, mx0, 2));
        mx1 = fmaxf(mx1, __shfl_xor_sync(0xffffffffu, mx1, 1));
        mx1 = fmaxf(mx1, __shfl_xor_sync(0xffffffffu, mx1, 2));
        float mn0 = fmaxf(m0, mx0), mn1 = fmaxf(m1, mx1);
        float al0 = __expf(m0 - mn0), al1 = __expf(m1 - mn1);
        m0 = mn0; m1 = mn1;

        uint32_t p01[8], p23[8];
        float sum0 = 0.f, sum1 = 0.f;
        #pragma unroll
        for (int nt = 0; nt < 8; nt++) {
            float p0 = __expf(s[nt][0] - mn0);
            float p1 = __expf(s[nt][1] - mn0);
            float p2 = __expf(s[nt][2] - mn1);
            float p3 = __expf(s[nt][3] - mn1);
            sum0 += p0 + p1;  sum1 += p2 + p3;
            p01[nt] = pack_h2(p0, p1);
            p23[nt] = pack_h2(p2, p3);
        }
        sum0 += __shfl_xor_sync(0xffffffffu, sum0, 1);
        sum0 += __shfl_xor_sync(0xffffffffu, sum0, 2);
        sum1 += __shfl_xor_sync(0xffffffffu, sum1, 1);
        sum1 += __shfl_xor_sync(0xffffffffu, sum1, 2);
        l0 = l0 * al0 + sum0;
        l1 = l1 * al1 + sum1;

        // rescale Y
        #pragma unroll
        for (int dt = 0; dt < 8; dt++) {
            yacc[dt][0] *= al0; yacc[dt][1] *= al0;
            yacc[dt][2] *= al1; yacc[dt][3] *= al1;
        }

        // ---- Y += P V^T: 64 keys in 4 k-steps ----
        #pragma unroll
        for (int ks = 0; ks < 4; ks++) {
            uint32_t a_[4] = { p01[2 * ks], p23[2 * ks], p01[2 * ks + 1], p23[2 * ks + 1] };
            #pragma unroll
            for (int dt = 0; dt < 8; dt++) {
                int dim = dt * 8 + tg;
                uint32_t b_[2] = { sV[dim][t4 + 8 * ks], sV[dim][t4 + 4 + 8 * ks] };
                mma16816(yacc[dt], a_, b_);
            }
        }
    }

    // ---- epilogue: divide by denom, write y ----
    float li0 = 1.f / l0, li1 = 1.f / l1;
    int tok0 = q0 + wid * 16 + tg;
    #pragma unroll
    for (int dt = 0; dt < 8; dt++) {
        int dim = dt * 8 + t4 * 2;
        float* o = y + ((size_t)(bh * 64 + dim)) * NTOK;
        o[tok0]            = yacc[dt][0] * li0;
        o[NTOK + tok0]     = yacc[dt][1] * li0;
        o[tok0 + 8]        = yacc[dt][2] * li1;
        o[NTOK + tok0 + 8] = yacc[dt][3] * li1;
    }
}

// ---------------------------------------------------------------------------
// SGEMM + folded BatchNorm (unchanged)
// ---------------------------------------------------------------------------
__global__ __launch_bounds__(256) void gemm_bn_kernel(
    const float* __restrict__ A, const float* __restrict__ B, float* __restrict__ C,
    int M, int N, int K,
    const float* __restrict__ gg, const float* __restrict__ bb,
    const float* __restrict__ mm, const float* __restrict__ vv)
{
    __shared__ float sA[16][68];
    __shared__ float sB[16][64];

    const int tid = threadIdx.x;
    const int tn = tid & 15;
    const int tm = tid >> 4;
    const int m0 = blockIdx.y * 64, n0 = blockIdx.x * 64;
    const float* Bp = B + (size_t)blockIdx.z * (size_t)K * N;
    float* Cp = C + (size_t)blockIdx.z * (size_t)M * N;

    const int lm = tid >> 2;
    const int lk = (tid & 3) << 2;

    float acc[4][4] = {};

    for (int k0 = 0; k0 < K; k0 += 16) {
        float4 a4 = *(const float4*)&A[(size_t)(m0 + lm) * K + k0 + lk];
        sA[lk + 0][lm] = a4.x; sA[lk + 1][lm] = a4.y;
        sA[lk + 2][lm] = a4.z; sA[lk + 3][lm] = a4.w;
        #pragma unroll
        for (int r = 0; r < 4; r++) {
            int kk = r * 4 + (tid >> 6);
            int nn = tid & 63;
            sB[kk][nn] = Bp[(size_t)(k0 + kk) * N + n0 + nn];
        }
        __syncthreads();
        #pragma unroll
        for (int kk = 0; kk < 16; kk++) {
            float4 av = *(const float4*)&sA[kk][tm << 2];
            float4 bv = *(const float4*)&sB[kk][tn << 2];
            float a_[4] = {av.x, av.y, av.z, av.w};
            float b_[4] = {bv.x, bv.y, bv.z, bv.w};
            #pragma unroll
            for (int i = 0; i < 4; i++)
                #pragma unroll
                for (int j = 0; j < 4; j++)
                    acc[i][j] += a_[i] * b_[j];
        }
        __syncthreads();
    }
    #pragma unroll
    for (int i = 0; i < 4; i++) {
        int m = m0 + (tm << 2) + i;
        float sc = gg[m] * rsqrtf(vv[m] + EPSV);
        float sh = bb[m] - mm[m] * sc;
        float4 o;
        o.x = acc[i][0] * sc + sh;
        o.y = acc[i][1] * sc + sh;
        o.z = acc[i][2] * sc + sh;
        o.w = acc[i][3] * sc + sh;
        *(float4*)&Cp[(size_t)m * N + n0 + (tn << 2)] = o;
    }
}

// ---------------------------------------------------------------------------
// Depthwise 3x3 conv + BN accumulated into g_y (unchanged)
// ---------------------------------------------------------------------------
__global__ __launch_bounds__(256) void pe_kernel(
    const float* __restrict__ qkv, float* __restrict__ y,
    const float* __restrict__ w,
    const float* __restrict__ gg, const float* __restrict__ bb,
    const float* __restrict__ mm, const float* __restrict__ vv)
{
    const int idx = blockIdx.x * 256 + threadIdx.x;
    const int bi = idx >> 20;
    const int r  = idx & ((1 << 20) - 1);
    const int c  = r >> 12;
    const int pix = r & 4095;
    const int py = pix >> 6, px = pix & 63;
    const int head = c >> 6, dim = c & 63;

    const float* vch = qkv + ((size_t)bi * 512 + head * 128 + 64 + dim) * NTOK;
    const float* wc = w + c * 9;

    float s = 0.f;
    #pragma unroll
    for (int dy = -1; dy <= 1; dy++) {
        int yy = py + dy;
        if (yy < 0 || yy > 63) continue;
        #pragma unroll
        for (int dx = -1; dx <= 1; dx++) {
            int xx = px + dx;
            if (xx < 0 || xx > 63) continue;
            s += vch[yy * 64 + xx] * wc[(dy + 1) * 3 + (dx + 1)];
        }
    }
    float sc = gg[c] * rsqrtf(vv[c] + EPSV);
    y[idx] += s * sc + (bb[c] - mm[c] * sc);
}

// ---------------------------------------------------------------------------
extern "C" void kernel_launch(void* const* d_in, const int* in_sizes, int n_in,
                              void* d_out, int out_size)
{
    const float* x      = (const float*)d_in[0];
    const float* qkv_w  = (const float*)d_in[1];
    const float* qkv_g  = (const float*)d_in[2];
    const float* qkv_b  = (const float*)d_in[3];
    const float* qkv_m  = (const float*)d_in[4];
    const float* qkv_v  = (const float*)d_in[5];
    const float* proj_w = (const float*)d_in[6];
    const float* proj_g = (const float*)d_in[7];
    const float* proj_b = (const float*)d_in[8];
    const float* proj_m = (const float*)d_in[9];
    const float* proj_v = (const float*)d_in[10];
    const float* pe_w   = (const float*)d_in[11];
    const float* pe_g   = (const float*)d_in[12];
    const float* pe_b   = (const float*)d_in[13];
    const float* pe_m   = (const float*)d_in[14];
    const float* pe_v   = (const float*)d_in[15];
    float* out = (float*)d_out;

    float* qkv_ptr = nullptr;
    float* y_ptr = nullptr;
    cudaGetSymbolAddress((void**)&qkv_ptr, g_qkv);
    cudaGetSymbolAddress((void**)&y_ptr, g_y);

    // 1) QKV 1x1 conv + BN
    gemm_bn_kernel<<<dim3(64, 8, 2), 256>>>(qkv_w, x, qkv_ptr, 512, 4096, 256,
                                            qkv_g, qkv_b, qkv_m, qkv_v);
    // 2) HMMA fp16 flash attention -> g_y
    attn_mma_kernel<<<dim3(32, 8), 256>>>(qkv_ptr, y_ptr);
    // 3) PE depthwise conv + BN accumulate
    pe_kernel<<<8192, 256>>>(qkv_ptr, y_ptr, pe_w, pe_g, pe_b, pe_m, pe_v);
    // 4) proj 1x1 conv + BN -> out
    gemm_bn_kernel<<<dim3(64, 4, 2), 256>>>(proj_w, y_ptr, out, 256, 4096, 256,
                                            proj_g, proj_b, proj_m, proj_v);
}

// round 7
// speedup vs baseline: 4.5373x; 1.8229x over previous
#include <cuda_runtime.h>
#include <cuda_bf16.h>
#include <cuda_fp16.h>
#include <cstdint>
#include <cstddef>

#define EPSV 1e-5f
#define NTOK 4096

// Scratch (no allocations allowed)
__device__ float g_qkv[2u * 512u * 4096u];   // 16 MB fp32 qkv activations
__device__ float g_y[2u * 256u * 4096u];     //  8 MB attention + pe output

__device__ __forceinline__ uint32_t pack_h2(float a, float b) {
    __half2 h = __floats2half2_rn(a, b);
    return *reinterpret_cast<uint32_t*>(&h);
}
__device__ __forceinline__ uint32_t pack_bf_hi(float a, float b, uint32_t& lo) {
    __nv_bfloat16 ah = __float2bfloat16_rn(a), bh = __float2bfloat16_rn(b);
    __nv_bfloat162 L = __floats2bfloat162_rn(a - __bfloat162float(ah),
                                             b - __bfloat162float(bh));
    lo = *reinterpret_cast<uint32_t*>(&L);
    __nv_bfloat162 H = __halves2bfloat162(ah, bh);
    return *reinterpret_cast<uint32_t*>(&H);
}

// mma.sync m16n8k16 row.col f32 += f16*f16
__device__ __forceinline__ void mma16816(float* c, const uint32_t* a, const uint32_t* b) {
    asm volatile(
        "mma.sync.aligned.m16n8k16.row.col.f32.f16.f16.f32 "
        "{%0,%1,%2,%3}, {%4,%5,%6,%7}, {%8,%9}, {%0,%1,%2,%3};"
        : "+f"(c[0]), "+f"(c[1]), "+f"(c[2]), "+f"(c[3])
        : "r"(a[0]), "r"(a[1]), "r"(a[2]), "r"(a[3]), "r"(b[0]), "r"(b[1]));
}
// mma.sync m16n8k16 row.col f32 += bf16*bf16
__device__ __forceinline__ void mma16816bf(float* c, const uint32_t* a, const uint32_t* b) {
    asm volatile(
        "mma.sync.aligned.m16n8k16.row.col.f32.bf16.bf16.f32 "
        "{%0,%1,%2,%3}, {%4,%5,%6,%7}, {%8,%9}, {%0,%1,%2,%3};"
        : "+f"(c[0]), "+f"(c[1]), "+f"(c[2]), "+f"(c[3])
        : "r"(a[0]), "r"(a[1]), "r"(a[2]), "r"(a[3]), "r"(b[0]), "r"(b[1]));
}

// ---------------------------------------------------------------------------
// HMMA GEMM + folded BatchNorm, bf16 hi/lo 3-term (fp32-level accuracy).
// C[b][m][n] = BN( sum_k A[m][k] * B[b][k][n] ),  A row-major MxK, B KxN.
// CTA tile 128m x 64n, 8 warps x 16 m-rows, K chunked by 32, reg-preload pipe.
// ---------------------------------------------------------------------------
__global__ __launch_bounds__(256) void gemm_bn_tc(
    const float* __restrict__ A, const float* __restrict__ B, float* __restrict__ C,
    int M, int N, int K,
    const float* __restrict__ gg, const float* __restrict__ bb,
    const float* __restrict__ mm, const float* __restrict__ vv)
{
    // u32 = bf16x2 pairs. Row stride 36 -> bank(36r + t4) = 4r + t4, conflict-free.
    __shared__ uint32_t sA[128][36];   // [m][kpair]: hi 0..15, lo 16..31
    __shared__ uint32_t sB[64][36];    // [n][kpair]: hi 0..15, lo 16..31

    const int tid = threadIdx.x, wid = tid >> 5, lane = tid & 31;
    const int tg = lane >> 2, t4 = lane & 3;
    const int m0 = blockIdx.y * 128, n0 = blockIdx.x * 64;
    const float* Bp = B + (size_t)blockIdx.z * (size_t)K * N;
    float* Cp = C + (size_t)blockIdx.z * (size_t)M * N;

    // staging assignments
    const int rA = tid >> 1, hA = tid & 1;          // A: row, 16-float half
    const int nB = tid & 63, kp0 = tid >> 6;        // B: col, kpair group (0..3)

    const int nchunk = K >> 5;                      // K/32

    // preload chunk 0
    float4 axf[4];
    float bxk[4][2];
    {
        const float* ap = A + (size_t)(m0 + rA) * K + hA * 16;
        #pragma unroll
        for (int i = 0; i < 4; i++) axf[i] = *(const float4*)(ap + 4 * i);
        #pragma unroll
        for (int i = 0; i < 4; i++) {
            int kp = kp0 + 4 * i;
            bxk[i][0] = Bp[(size_t)(2 * kp) * N + n0 + nB];
            bxk[i][1] = Bp[(size_t)(2 * kp + 1) * N + n0 + nB];
        }
    }

    float c[8][4];
    #pragma unroll
    for (int i = 0; i < 8; i++)
        #pragma unroll
        for (int j = 0; j < 4; j++) c[i][j] = 0.f;

    for (int ch = 0; ch < nchunk; ch++) {
        if (ch) __syncthreads();       // previous mma done reading smem
        // store staged -> smem (bf16 hi/lo split)
        #pragma unroll
        for (int i = 0; i < 4; i++) {
            uint32_t lo0, lo1;
            uint32_t hi0 = pack_bf_hi(axf[i].x, axf[i].y, lo0);
            uint32_t hi1 = pack_bf_hi(axf[i].z, axf[i].w, lo1);
            int kp = hA * 8 + 2 * i;
            sA[rA][kp] = hi0;       sA[rA][kp + 1] = hi1;
            sA[rA][16 + kp] = lo0;  sA[rA][16 + kp + 1] = lo1;
        }
        #pragma unroll
        for (int i = 0; i < 4; i++) {
            uint32_t lo;
            uint32_t hi = pack_bf_hi(bxk[i][0], bxk[i][1], lo);
            sB[nB][kp0 + 4 * i] = hi;
            sB[nB][16 + kp0 + 4 * i] = lo;
        }
        __syncthreads();

        // preload next chunk (overlaps mma)
        if (ch + 1 < nchunk) {
            const int k0 = (ch + 1) * 32;
            const float* ap = A + (size_t)(m0 + rA) * K + k0 + hA * 16;
            #pragma unroll
            for (int i = 0; i < 4; i++) axf[i] = *(const float4*)(ap + 4 * i);
            #pragma unroll
            for (int i = 0; i < 4; i++) {
                int kp = kp0 + 4 * i;
                bxk[i][0] = Bp[(size_t)(k0 + 2 * kp) * N + n0 + nB];
                bxk[i][1] = Bp[(size_t)(k0 + 2 * kp + 1) * N + n0 + nB];
            }
        }

        // mma: 2 ksteps x 8 n-tiles x 3 terms
        const int r0 = wid * 16 + tg, r1 = r0 + 8;
        #pragma unroll
        for (int ks = 0; ks < 2; ks++) {
            int ca = t4 + 8 * ks;
            uint32_t ah[4] = { sA[r0][ca],      sA[r1][ca],
                               sA[r0][ca + 4],  sA[r1][ca + 4] };
            uint32_t al[4] = { sA[r0][16 + ca],     sA[r1][16 + ca],
                               sA[r0][16 + ca + 4], sA[r1][16 + ca + 4] };
            #pragma unroll
            for (int nt = 0; nt < 8; nt++) {
                int n = nt * 8 + tg;
                uint32_t bh_[2] = { sB[n][ca], sB[n][ca + 4] };
                uint32_t bl_[2] = { sB[n][16 + ca], sB[n][16 + ca + 4] };
                mma16816bf(c[nt], ah, bh_);
                mma16816bf(c[nt], ah, bl_);
                mma16816bf(c[nt], al, bh_);
            }
        }
    }

    // epilogue: BN + store (c0,c1 = row r0 cols n,n+1; c2,c3 = row r1)
    const int r0 = m0 + wid * 16 + tg, r1 = r0 + 8;
    float sc0 = gg[r0] * rsqrtf(vv[r0] + EPSV), sh0 = bb[r0] - mm[r0] * sc0;
    float sc1 = gg[r1] * rsqrtf(vv[r1] + EPSV), sh1 = bb[r1] - mm[r1] * sc1;
    #pragma unroll
    for (int nt = 0; nt < 8; nt++) {
        int n = n0 + nt * 8 + 2 * t4;
        *(float2*)&Cp[(size_t)r0 * N + n] = make_float2(c[nt][0] * sc0 + sh0,
                                                        c[nt][1] * sc0 + sh0);
        *(float2*)&Cp[(size_t)r1 * N + n] = make_float2(c[nt][2] * sc1 + sh1,
                                                        c[nt][3] * sc1 + sh1);
    }
}

// ---------------------------------------------------------------------------
// Flash attention via warp-level fp16 HMMA (single-term). Unchanged from R6.
// ---------------------------------------------------------------------------
__global__ __launch_bounds__(256, 1) void attn_mma_kernel(
    const float* __restrict__ qkv, float* __restrict__ y)
{
    __shared__ uint32_t sQ[128][20];
    __shared__ uint32_t sK[64][20];
    __shared__ uint32_t sV[64][36];

    const int tid = threadIdx.x, wid = tid >> 5, lane = tid & 31;
    const int tg = lane >> 2;
    const int t4 = lane & 3;
    const int bh = blockIdx.y, bi = bh >> 2, h = bh & 3;
    const int q0 = blockIdx.x * 128;

    const float* qp = qkv + ((size_t)bi * 512 + h * 128) * NTOK;
    const float* kp = qp + (size_t)32 * NTOK;
    const float* vp = qp + (size_t)64 * NTOK;

    {
        const float scale = 0.17677669529663687f;
        int row = tid & 127, dp0 = tid >> 7;
        #pragma unroll
        for (int dp = dp0; dp < 16; dp += 2) {
            float x0 = qp[(size_t)(2 * dp) * NTOK + q0 + row] * scale;
            float x1 = qp[(size_t)(2 * dp + 1) * NTOK + q0 + row] * scale;
            sQ[row][dp] = pack_h2(x0, x1);
        }
    }
    __syncthreads();

    uint32_t qh[2][4];
    {
        int r0 = wid * 16 + tg, r1 = r0 + 8;
        #pragma unroll
        for (int ks = 0; ks < 2; ks++) {
            int cidx = t4 + 8 * ks;
            qh[ks][0] = sQ[r0][cidx];     qh[ks][1] = sQ[r1][cidx];
            qh[ks][2] = sQ[r0][cidx + 4]; qh[ks][3] = sQ[r1][cidx + 4];
        }
    }

    const int kkey = tid & 63, kdp0 = tid >> 6;
    const int vkp = tid & 31, vd0 = tid >> 5;

    float kx[4][2];
    float2 vx[8];
    {
        #pragma unroll
        for (int i = 0; i < 4; i++) {
            int dp = kdp0 + 4 * i;
            kx[i][0] = kp[(size_t)(2 * dp) * NTOK + kkey];
            kx[i][1] = kp[(size_t)(2 * dp + 1) * NTOK + kkey];
        }
        #pragma unroll
        for (int i = 0; i < 8; i++) {
            int d = vd0 + 8 * i;
            vx[i] = *(const float2*)(vp + (size_t)d * NTOK + 2 * vkp);
        }
    }

    float m0 = -3e38f, m1 = -3e38f, l0 = 0.f, l1 = 0.f;
    float yacc[8][4];
    #pragma unroll
    for (int i = 0; i < 8; i++)
        #pragma unroll
        for (int j = 0; j < 4; j++) yacc[i][j] = 0.f;

    for (int blk = 0; blk < 64; blk++) {
        __syncthreads();
        #pragma unroll
        for (int i = 0; i < 4; i++)
            sK[kkey][kdp0 + 4 * i] = pack_h2(kx[i][0], kx[i][1]);
        #pragma unroll
        for (int i = 0; i < 8; i++)
            sV[vd0 + 8 * i][vkp] = pack_h2(vx[i].x, vx[i].y);
        __syncthreads();

        if (blk < 63) {
            const int k0t = (blk + 1) * 64;
            #pragma unroll
            for (int i = 0; i < 4; i++) {
                int dp = kdp0 + 4 * i;
                kx[i][0] = kp[(size_t)(2 * dp) * NTOK + k0t + kkey];
                kx[i][1] = kp[(size_t)(2 * dp + 1) * NTOK + k0t + kkey];
            }
            #pragma unroll
            for (int i = 0; i < 8; i++) {
                int d = vd0 + 8 * i;
                vx[i] = *(const float2*)(vp + (size_t)d * NTOK + k0t + 2 * vkp);
            }
        }

        float s[8][4];
        #pragma unroll
        for (int nt = 0; nt < 8; nt++) {
            s[nt][0] = s[nt][1] = s[nt][2] = s[nt][3] = 0.f;
            int key = nt * 8 + tg;
            #pragma unroll
            for (int ks = 0; ks < 2; ks++) {
                uint32_t b_[2] = { sK[key][t4 + 8 * ks], sK[key][t4 + 4 + 8 * ks] };
                mma16816(s[nt], qh[ks], b_);
            }
        }

        float mx0 = -3e38f, mx1 = -3e38f;
        #pragma unroll
        for (int nt = 0; nt < 8; nt++) {
            mx0 = fmaxf(mx0, fmaxf(s[nt][0], s[nt][1]));
            mx1 = fmaxf(mx1, fmaxf(s[nt][2], s[nt][3]));
        }
        mx0 = fmaxf(mx0, __shfl_xor_sync(0xffffffffu, mx0, 1));
        mx0 = fmaxf(mx0, __shfl_xor_sync(0xffffffffu, mx0, 2));
        mx1 = fmaxf(mx1, __shfl_xor_sync(0xffffffffu, mx1, 1));
        mx1 = fmaxf(mx1, __shfl_xor_sync(0xffffffffu, mx1, 2));
        float mn0 = fmaxf(m0, mx0), mn1 = fmaxf(m1, mx1);
        float al0 = __expf(m0 - mn0), al1 = __expf(m1 - mn1);
        m0 = mn0; m1 = mn1;

        uint32_t p01[8], p23[8];
        float sum0 = 0.f, sum1 = 0.f;
        #pragma unroll
        for (int nt = 0; nt < 8; nt++) {
            float p0 = __expf(s[nt][0] - mn0);
            float p1 = __expf(s[nt][1] - mn0);
            float p2 = __expf(s[nt][2] - mn1);
            float p3 = __expf(s[nt][3] - mn1);
            sum0 += p0 + p1;  sum1 += p2 + p3;
            p01[nt] = pack_h2(p0, p1);
            p23[nt] = pack_h2(p2, p3);
        }
        sum0 += __shfl_xor_sync(0xffffffffu, sum0, 1);
        sum0 += __shfl_xor_sync(0xffffffffu, sum0, 2);
        sum1 += __shfl_xor_sync(0xffffffffu, sum1, 1);
        sum1 += __shfl_xor_sync(0xffffffffu, sum1, 2);
        l0 = l0 * al0 + sum0;
        l1 = l1 * al1 + sum1;

        #pragma unroll
        for (int dt = 0; dt < 8; dt++) {
            yacc[dt][0] *= al0; yacc[dt][1] *= al0;
            yacc[dt][2] *= al1; yacc[dt][3] *= al1;
        }

        #pragma unroll
        for (int ks = 0; ks < 4; ks++) {
            uint32_t a_[4] = { p01[2 * ks], p23[2 * ks], p01[2 * ks + 1], p23[2 * ks + 1] };
            #pragma unroll
            for (int dt = 0; dt < 8; dt++) {
                int dim = dt * 8 + tg;
                uint32_t b_[2] = { sV[dim][t4 + 8 * ks], sV[dim][t4 + 4 + 8 * ks] };
                mma16816(yacc[dt], a_, b_);
            }
        }
    }

    float li0 = 1.f / l0, li1 = 1.f / l1;
    int tok0 = q0 + wid * 16 + tg;
    #pragma unroll
    for (int dt = 0; dt < 8; dt++) {
        int dim = dt * 8 + t4 * 2;
        float* o = y + ((size_t)(bh * 64 + dim)) * NTOK;
        o[tok0]            = yacc[dt][0] * li0;
        o[NTOK + tok0]     = yacc[dt][1] * li0;
        o[tok0 + 8]        = yacc[dt][2] * li1;
        o[NTOK + tok0 + 8] = yacc[dt][3] * li1;
    }
}

// ---------------------------------------------------------------------------
// Depthwise 3x3 conv + BN accumulated into g_y (unchanged)
// ---------------------------------------------------------------------------
__global__ __launch_bounds__(256) void pe_kernel(
    const float* __restrict__ qkv, float* __restrict__ y,
    const float* __restrict__ w,
    const float* __restrict__ gg, const float* __restrict__ bb,
    const float* __restrict__ mm, const float* __restrict__ vv)
{
    const int idx = blockIdx.x * 256 + threadIdx.x;
    const int bi = idx >> 20;
    const int r  = idx & ((1 << 20) - 1);
    const int c  = r >> 12;
    const int pix = r & 4095;
    const int py = pix >> 6, px = pix & 63;
    const int head = c >> 6, dim = c & 63;

    const float* vch = qkv + ((size_t)bi * 512 + head * 128 + 64 + dim) * NTOK;
    const float* wc = w + c * 9;

    float s = 0.f;
    #pragma unroll
    for (int dy = -1; dy <= 1; dy++) {
        int yy = py + dy;
        if (yy < 0 || yy > 63) continue;
        #pragma unroll
        for (int dx = -1; dx <= 1; dx++) {
            int xx = px + dx;
            if (xx < 0 || xx > 63) continue;
            s += vch[yy * 64 + xx] * wc[(dy + 1) * 3 + (dx + 1)];
        }
    }
    float sc = gg[c] * rsqrtf(vv[c] + EPSV);
    y[idx] += s * sc + (bb[c] - mm[c] * sc);
}

// ---------------------------------------------------------------------------
extern "C" void kernel_launch(void* const* d_in, const int* in_sizes, int n_in,
                              void* d_out, int out_size)
{
    const float* x      = (const float*)d_in[0];
    const float* qkv_w  = (const float*)d_in[1];
    const float* qkv_g  = (const float*)d_in[2];
    const float* qkv_b  = (const float*)d_in[3];
    const float* qkv_m  = (const float*)d_in[4];
    const float* qkv_v  = (const float*)d_in[5];
    const float* proj_w = (const float*)d_in[6];
    const float* proj_g = (const float*)d_in[7];
    const float* proj_b = (const float*)d_in[8];
    const float* proj_m = (const float*)d_in[9];
    const float* proj_v = (const float*)d_in[10];
    const float* pe_w   = (const float*)d_in[11];
    const float* pe_g   = (const float*)d_in[12];
    const float* pe_b   = (const float*)d_in[13];
    const float* pe_m   = (const float*)d_in[14];
    const float* pe_v   = (const float*)d_in[15];
    float* out = (float*)d_out;

    float* qkv_ptr = nullptr;
    float* y_ptr = nullptr;
    cudaGetSymbolAddress((void**)&qkv_ptr, g_qkv);
    cudaGetSymbolAddress((void**)&y_ptr, g_y);

    // 1) QKV 1x1 conv + BN  (512x256 @ 256x4096, per batch)
    gemm_bn_tc<<<dim3(64, 4, 2), 256>>>(qkv_w, x, qkv_ptr, 512, 4096, 256,
                                        qkv_g, qkv_b, qkv_m, qkv_v);
    // 2) HMMA fp16 flash attention -> g_y
    attn_mma_kernel<<<dim3(32, 8), 256>>>(qkv_ptr, y_ptr);
    // 3) PE depthwise conv + BN accumulate
    pe_kernel<<<8192, 256>>>(qkv_ptr, y_ptr, pe_w, pe_g, pe_b, pe_m, pe_v);
    // 4) proj 1x1 conv + BN -> out
    gemm_bn_tc<<<dim3(64, 2, 2), 256>>>(proj_w, y_ptr, out, 256, 4096, 256,
                                        proj_g, proj_b, proj_m, proj_v);
}